// round 2
// baseline (speedup 1.0000x reference)
#include <cuda_runtime.h>

#define FDIM 128
#define KH 5
#define NMAX 100000
#define BN_EPS 1e-5f

// ---------------- device scratch (static, no allocs) ----------------
__device__ float g_h[(size_t)NMAX * FDIM];   // h = x + agg   (51.2 MB)
__device__ float g_y[(size_t)NMAX * FDIM];   // y1            (51.2 MB)
__device__ float g_hopw[8];
__device__ float g_st1[256];                 // [0:128) colsum, [128:256) colsumsq
__device__ float g_st2[256];
__device__ float g_a1[FDIM], g_c1[FDIM];     // BN1 fused scale/shift
__device__ float g_a2[FDIM], g_c2[FDIM];     // BN2 fused scale/shift

// ---------------- f32x2 helpers (sm_103a packed fp32 FMA) ----------------
__device__ __forceinline__ unsigned long long pk2(float lo, float hi) {
    unsigned long long r;
    asm("mov.b64 %0, {%1, %2};" : "=l"(r) : "f"(lo), "f"(hi));
    return r;
}
__device__ __forceinline__ float2 upk2(unsigned long long v) {
    float2 r;
    asm("mov.b64 {%0, %1}, %2;" : "=f"(r.x), "=f"(r.y) : "l"(v));
    return r;
}
#define FMA2(d, a, b) asm("fma.rn.f32x2 %0, %1, %2, %0;" : "+l"(d) : "l"(a), "l"(b))

// ---------------- kernel 0: softmax(hop_coef) + zero stats ----------------
__global__ void k_prep(const float* __restrict__ hop_coef) {
    int t = threadIdx.x;
    if (t < 256) { g_st1[t] = 0.f; g_st2[t] = 0.f; }
    if (t == 0) {
        float v[KH];
        float m = -1e30f;
        for (int i = 0; i < KH; i++) { v[i] = hop_coef[i]; m = fmaxf(m, v[i]); }
        float s = 0.f;
        for (int i = 0; i < KH; i++) { v[i] = expf(v[i] - m); s += v[i]; }
        float inv = 1.f / s;
        for (int i = 0; i < KH; i++) g_hopw[i] = v[i] * inv;
    }
}

// ---------------- kernel 1: g_h = node_embeddings (GIN self term) ----------------
__global__ void k_init(const float4* __restrict__ x, int n4) {
    float4* h4 = (float4*)g_h;
    for (int i = blockIdx.x * blockDim.x + threadIdx.x; i < n4;
         i += gridDim.x * blockDim.x)
        h4[i] = x[i];
}

// ---------------- kernel 2: scatter-add messages. one warp per edge ----------------
__global__ void k_scatter(const float* __restrict__ x,
                          const int* __restrict__ ei,
                          const int* __restrict__ ew, int E) {
    int warp = (blockIdx.x * blockDim.x + threadIdx.x) >> 5;
    int lane = threadIdx.x & 31;
    if (warp >= E) return;
    int d = ew[warp];
    if (d < 1 || d > KH) return;
    float w = g_hopw[d - 1];
    int r = ei[warp];           // edge_index[0][e]
    int c = ei[E + warp];       // edge_index[1][e]
    float4 v = ((const float4*)x)[(size_t)c * 32 + lane];
    v.x *= w; v.y *= w; v.z *= w; v.w *= w;
    atomicAdd(((float4*)g_h) + (size_t)r * 32 + lane, v);   // RED.128
}

// ---------------- GEMM + fused BN-stats epilogue ----------------
// PHASE 1: A = g_h (raw), Y = g_y, stats -> g_st1
// PHASE 2: A = g_y with fused relu(a1*y+c1), Y = out (d_out arg), stats -> g_st2
// Device globals are resolved INSIDE device code (never passed from host).
// Block: 256 threads, 64 rows x 128 cols per block.
template <int PHASE>
__global__ void k_gemm(const float* __restrict__ W,
                       float* __restrict__ OutY, int n) {
    const float* A = (PHASE == 1) ? g_h : g_y;
    float* Y       = (PHASE == 1) ? g_y : OutY;

    extern __shared__ float smem[];
    float* Ws = smem;                  // [128][128]
    float* As = smem + FDIM * FDIM;    // [64][128]
    __shared__ float sh_st[256];

    int tid = threadIdx.x;
    int tc = tid & 31, tr = tid >> 5;
    sh_st[tid] = 0.f;

    // stage W
    const float4* W4 = (const float4*)W;
    float4* Ws4 = (float4*)Ws;
    #pragma unroll 4
    for (int i = tid; i < FDIM * 32; i += 256) Ws4[i] = W4[i];

    // stage A tile (with fused BN1+ReLU transform in phase 2)
    int row0 = blockIdx.x * 64;
    float4* As4 = (float4*)As;
    const float4* A4 = (const float4*)A;
    #pragma unroll
    for (int i = tid; i < 64 * 32; i += 256) {
        int r = i >> 5, c4 = i & 31;
        float4 v;
        if (row0 + r < n) {
            v = A4[(size_t)(row0 + r) * 32 + c4];
            if (PHASE == 2) {
                float4 a = ((const float4*)g_a1)[c4];
                float4 b = ((const float4*)g_c1)[c4];
                v.x = fmaxf(fmaf(a.x, v.x, b.x), 0.f);
                v.y = fmaxf(fmaf(a.y, v.y, b.y), 0.f);
                v.z = fmaxf(fmaf(a.z, v.z, b.z), 0.f);
                v.w = fmaxf(fmaf(a.w, v.w, b.w), 0.f);
            }
        } else {
            v = make_float4(0.f, 0.f, 0.f, 0.f);
        }
        As4[i] = v;
    }
    __syncthreads();

    unsigned long long acc[4][4];
    #pragma unroll
    for (int p = 0; p < 4; p++)
        #pragma unroll
        for (int c = 0; c < 4; c++) acc[p][c] = 0ULL;

    int r0 = tr * 8;
    #pragma unroll 4
    for (int k = 0; k < FDIM; k++) {
        float4 wv = Ws4[k * 32 + tc];
        unsigned long long w0 = pk2(wv.x, wv.x);
        unsigned long long w1 = pk2(wv.y, wv.y);
        unsigned long long w2 = pk2(wv.z, wv.z);
        unsigned long long w3 = pk2(wv.w, wv.w);
        #pragma unroll
        for (int p = 0; p < 4; p++) {
            unsigned long long ap =
                pk2(As[(r0 + 2 * p) * FDIM + k], As[(r0 + 2 * p + 1) * FDIM + k]);
            FMA2(acc[p][0], ap, w0);
            FMA2(acc[p][1], ap, w1);
            FMA2(acc[p][2], ap, w2);
            FMA2(acc[p][3], ap, w3);
        }
    }

    // epilogue: store Y + per-column stats
    float cs[4] = {0.f, 0.f, 0.f, 0.f};
    float cq[4] = {0.f, 0.f, 0.f, 0.f};
    #pragma unroll
    for (int p = 0; p < 4; p++) {
        float2 c0 = upk2(acc[p][0]);
        float2 c1 = upk2(acc[p][1]);
        float2 c2 = upk2(acc[p][2]);
        float2 c3 = upk2(acc[p][3]);
        int r_lo = row0 + r0 + 2 * p;
        int r_hi = r_lo + 1;
        if (r_lo < n) {
            float4 o = make_float4(c0.x, c1.x, c2.x, c3.x);
            ((float4*)Y)[(size_t)r_lo * 32 + tc] = o;
            cs[0] += o.x; cs[1] += o.y; cs[2] += o.z; cs[3] += o.w;
            cq[0] += o.x * o.x; cq[1] += o.y * o.y;
            cq[2] += o.z * o.z; cq[3] += o.w * o.w;
        }
        if (r_hi < n) {
            float4 o = make_float4(c0.y, c1.y, c2.y, c3.y);
            ((float4*)Y)[(size_t)r_hi * 32 + tc] = o;
            cs[0] += o.x; cs[1] += o.y; cs[2] += o.z; cs[3] += o.w;
            cq[0] += o.x * o.x; cq[1] += o.y * o.y;
            cq[2] += o.z * o.z; cq[3] += o.w * o.w;
        }
    }
    #pragma unroll
    for (int c = 0; c < 4; c++) {
        atomicAdd(&sh_st[tc * 4 + c], cs[c]);
        atomicAdd(&sh_st[128 + tc * 4 + c], cq[c]);
    }
    __syncthreads();
    float* gst = (PHASE == 1) ? g_st1 : g_st2;
    atomicAdd(&gst[tid], sh_st[tid]);
}

// ---------------- BN finalize: stats -> fused scale/shift ----------------
template <int PHASE>
__global__ void k_bnfin(const float* __restrict__ gamma,
                        const float* __restrict__ beta, float invN) {
    int i = threadIdx.x;  // 128 threads
    const float* st = (PHASE == 1) ? g_st1 : g_st2;
    float mean = st[i] * invN;
    float var = st[i + 128] * invN - mean * mean;
    float s = gamma[i] * rsqrtf(var + BN_EPS);
    if (PHASE == 1) { g_a1[i] = s; g_c1[i] = beta[i] - mean * s; }
    else            { g_a2[i] = s; g_c2[i] = beta[i] - mean * s; }
}

// ---------------- final BN2 + ReLU, in place on d_out ----------------
__global__ void k_final(float4* __restrict__ y, int n4) {
    for (int i = blockIdx.x * blockDim.x + threadIdx.x; i < n4;
         i += gridDim.x * blockDim.x) {
        int c4 = i & 31;
        float4 a = ((const float4*)g_a2)[c4];
        float4 b = ((const float4*)g_c2)[c4];
        float4 v = y[i];
        v.x = fmaxf(fmaf(a.x, v.x, b.x), 0.f);
        v.y = fmaxf(fmaf(a.y, v.y, b.y), 0.f);
        v.z = fmaxf(fmaf(a.z, v.z, b.z), 0.f);
        v.w = fmaxf(fmaf(a.w, v.w, b.w), 0.f);
        y[i] = v;
    }
}

// ---------------- launcher ----------------
extern "C" void kernel_launch(void* const* d_in, const int* in_sizes, int n_in,
                              void* d_out, int out_size) {
    const float* x    = (const float*)d_in[0];   // [N,128]
    const int*   ei   = (const int*)  d_in[1];   // [2,E]
    const int*   ew   = (const int*)  d_in[2];   // [E]
    const float* hop  = (const float*)d_in[3];   // [5]
    const float* W1   = (const float*)d_in[4];   // [128,128]
    const float* g1   = (const float*)d_in[6];
    const float* be1  = (const float*)d_in[7];
    const float* W2   = (const float*)d_in[8];
    const float* g2   = (const float*)d_in[10];
    const float* be2  = (const float*)d_in[11];
    float* out = (float*)d_out;

    int n = in_sizes[0] / FDIM;   // 100000
    int E = in_sizes[2];          // 1600000
    int n4 = n * 32;
    float invN = 1.f / (float)n;

    const int SMEM = (FDIM * FDIM + 64 * FDIM) * sizeof(float);  // 98304 B
    cudaFuncSetAttribute(k_gemm<1>, cudaFuncAttributeMaxDynamicSharedMemorySize, SMEM);
    cudaFuncSetAttribute(k_gemm<2>, cudaFuncAttributeMaxDynamicSharedMemorySize, SMEM);

    k_prep<<<1, 256>>>(hop);
    k_init<<<2048, 256>>>((const float4*)x, n4);
    k_scatter<<<(E + 7) / 8, 256>>>(x, ei, ew, E);

    int gblocks = (n + 63) / 64;
    k_gemm<1><<<gblocks, 256, SMEM>>>(W1, nullptr, n);
    k_bnfin<1><<<1, 128>>>(g1, be1, invN);
    k_gemm<2><<<gblocks, 256, SMEM>>>(W2, out, n);
    k_bnfin<2><<<1, 128>>>(g2, be2, invN);
    k_final<<<2048, 256>>>((float4*)out, n4);
}